// round 2
// baseline (speedup 1.0000x reference)
#include <cuda_runtime.h>
#include <math.h>

// Problem constants
#define HID    1024
#define VOCAB  32000
#define BATCH  8
#define SEQ    512
#define INDIM  768
#define MROWS  (BATCH*SEQ)      // 4096
#define GATES  (3*HID)          // 3072

// ---------------- scratch (no allocation allowed -> device globals) -----------
__device__ float g_h0[2*BATCH*HID];          // initial hidden per layer [L][B][H]
__device__ float g_hA[BATCH*HID];            // ping
__device__ float g_hB[BATCH*HID];            // pong
__device__ float g_xg[(size_t)MROWS*GATES];  // precomputed input gates (reused per layer)
__device__ float g_y0[(size_t)MROWS*HID];    // layer0 outputs
__device__ float g_y1[(size_t)MROWS*HID];    // layer1 outputs
__device__ unsigned int          g_barcnt = 0;
__device__ volatile unsigned int g_bargen = 0;

// ---------------- h0: global context + c2h projection --------------------------
__global__ void h0_kernel(const float* __restrict__ concepts,
                          const float* __restrict__ c2h_w,
                          const float* __restrict__ c2h_b)
{
    __shared__ float ctx[INDIM];
    int b = blockIdx.x, tid = threadIdx.x;
    for (int d = tid; d < INDIM; d += blockDim.x) {
        float s = 0.f;
        #pragma unroll
        for (int n = 0; n < 16; n++) s += concepts[(b*16 + n)*INDIM + d];
        ctx[d] = s * (1.0f/16.0f);
    }
    __syncthreads();
    for (int k = tid; k < 2*HID; k += blockDim.x) {
        const float* w = c2h_w + (size_t)k*INDIM;
        float acc = 0.f;
        #pragma unroll 4
        for (int d = 0; d < INDIM; d += 4) {
            acc += ctx[d+0]*w[d+0] + ctx[d+1]*w[d+1]
                 + ctx[d+2]*w[d+2] + ctx[d+3]*w[d+3];
        }
        acc += c2h_b[k];
        int l = k >> 10, j = k & (HID-1);
        g_h0[(l*BATCH + b)*HID + j] = acc;
    }
}

// ---------------- SGEMM: C[M,N] = A[M,K] * B[N,K]^T + bias[N] ------------------
// A optionally row-gathered (embedding lookup fused into GEMM).
// 128x128 tile, BK=16, 256 threads, 8x8 per-thread micro-tile, double buffered.
#define BM 128
#define BN 128
#define BK 16
#define PAD 4

template<bool GATHER>
__global__ void __launch_bounds__(256, 2)
sgemm_tn(const float* __restrict__ A, const float* __restrict__ B,
         const float* __restrict__ bias, float* __restrict__ C,
         const int* __restrict__ gidx, int M, int N, int K)
{
    __shared__ float As[2][BK][BM+PAD];
    __shared__ float Bs[2][BK][BN+PAD];

    const int tid = threadIdx.x;
    const int bm  = blockIdx.y * BM;
    const int bn  = blockIdx.x * BN;

    // load mapping: 512 float4 per tile, 2 per thread
    int smRow[2], c4v[2], aRow[2], bRow[2];
    #pragma unroll
    for (int u = 0; u < 2; u++) {
        int f = tid + u*256;
        smRow[u] = f >> 2;
        c4v[u]   = (f & 3) << 2;
        int gr   = bm + smRow[u];
        aRow[u]  = GATHER ? gidx[gr] : gr;
        bRow[u]  = bn + smRow[u];
    }

    float4 ra[2], rb[2];
    auto loadTiles = [&](int kt) {
        int k0 = kt * BK;
        #pragma unroll
        for (int u = 0; u < 2; u++) {
            ra[u] = *reinterpret_cast<const float4*>(A + (size_t)aRow[u]*K + k0 + c4v[u]);
            rb[u] = *reinterpret_cast<const float4*>(B + (size_t)bRow[u]*K + k0 + c4v[u]);
        }
    };
    auto storeTiles = [&](int buf) {
        #pragma unroll
        for (int u = 0; u < 2; u++) {
            int r = smRow[u], c = c4v[u];
            As[buf][c+0][r] = ra[u].x; As[buf][c+1][r] = ra[u].y;
            As[buf][c+2][r] = ra[u].z; As[buf][c+3][r] = ra[u].w;
            Bs[buf][c+0][r] = rb[u].x; Bs[buf][c+1][r] = rb[u].y;
            Bs[buf][c+2][r] = rb[u].z; Bs[buf][c+3][r] = rb[u].w;
        }
    };

    const int tm = (tid >> 4) << 3;   // 0..120
    const int tn = (tid & 15) << 3;   // 0..120
    float acc[8][8];
    #pragma unroll
    for (int i = 0; i < 8; i++)
        #pragma unroll
        for (int j = 0; j < 8; j++) acc[i][j] = 0.f;

    const int nk = K / BK;
    loadTiles(0); storeTiles(0); __syncthreads();

    for (int kt = 0; kt < nk; kt++) {
        int cur = kt & 1;
        if (kt + 1 < nk) loadTiles(kt + 1);
        #pragma unroll
        for (int kk = 0; kk < BK; kk++) {
            float a[8], b[8];
            *reinterpret_cast<float4*>(&a[0]) = *reinterpret_cast<const float4*>(&As[cur][kk][tm]);
            *reinterpret_cast<float4*>(&a[4]) = *reinterpret_cast<const float4*>(&As[cur][kk][tm+4]);
            *reinterpret_cast<float4*>(&b[0]) = *reinterpret_cast<const float4*>(&Bs[cur][kk][tn]);
            *reinterpret_cast<float4*>(&b[4]) = *reinterpret_cast<const float4*>(&Bs[cur][kk][tn+4]);
            #pragma unroll
            for (int i = 0; i < 8; i++)
                #pragma unroll
                for (int j = 0; j < 8; j++)
                    acc[i][j] += a[i] * b[j];
        }
        if (kt + 1 < nk) storeTiles(cur ^ 1);
        __syncthreads();
    }

    float bv[8];
    #pragma unroll
    for (int j = 0; j < 8; j++) bv[j] = bias[bn + tn + j];
    #pragma unroll
    for (int i = 0; i < 8; i++) {
        size_t r = (size_t)(bm + tm + i) * N + bn + tn;
        float4 v0, v1;
        v0.x = acc[i][0]+bv[0]; v0.y = acc[i][1]+bv[1];
        v0.z = acc[i][2]+bv[2]; v0.w = acc[i][3]+bv[3];
        v1.x = acc[i][4]+bv[4]; v1.y = acc[i][5]+bv[5];
        v1.z = acc[i][6]+bv[6]; v1.w = acc[i][7]+bv[7];
        *reinterpret_cast<float4*>(C + r)     = v0;
        *reinterpret_cast<float4*>(C + r + 4) = v1;
    }
}

// ---------------- persistent GRU layer kernel ----------------------------------
// 128 blocks x 256 threads, all co-resident (<=148 SMs) -> hand-rolled grid barrier.
// Block owns 8 hidden units j, all 8 batches. 4 threads cooperate per (b,j) pair.
__device__ __forceinline__ void grid_sync()
{
    __threadfence();
    __syncthreads();
    if (threadIdx.x == 0) {
        unsigned int gen = g_bargen;
        if (atomicAdd(&g_barcnt, 1) == gridDim.x - 1) {
            g_barcnt = 0;
            __threadfence();
            g_bargen = gen + 1;
        } else {
            while (g_bargen == gen) { }
        }
    }
    __syncthreads();
}

#define HPAD (HID+4)

__global__ void __launch_bounds__(256, 1)
gru_kernel(const float* __restrict__ xg,    // [MROWS, 3H], row = b*SEQ+s
           const float* __restrict__ whh,   // [3H, H]
           const float* __restrict__ bhh,   // [3H]
           const float* __restrict__ h0,    // [B, H]
           float* __restrict__ y,           // [B, SEQ, H]
           float* __restrict__ hping,
           float* __restrict__ hpong)
{
    __shared__ float hs[BATCH * HPAD];

    const int tid  = threadIdx.x;
    const int sub  = tid & 3;          // k-split within a pair
    const int pair = tid >> 2;         // 0..63
    const int b    = pair & 7;
    const int jl   = pair >> 3;        // 0..7
    const int j    = blockIdx.x * 8 + jl;

    const float* w_r = whh + (size_t)(0*HID + j) * HID;
    const float* w_z = whh + (size_t)(1*HID + j) * HID;
    const float* w_n = whh + (size_t)(2*HID + j) * HID;
    const float br = bhh[j], bz = bhh[HID + j], bn_ = bhh[2*HID + j];

    for (int s = 0; s < SEQ; s++) {
        const float* hsrc = (s == 0) ? h0 : ((s & 1) ? hping : hpong);
        float*       hdst = (s & 1) ? hpong : hping;

        // stage current hidden state into smem (L2-coherent reads)
        const float4* h4 = reinterpret_cast<const float4*>(hsrc);
        for (int i = tid; i < (BATCH*HID)/4; i += 256) {
            float4 v = __ldcg(h4 + i);
            int idx = i << 2;
            int bb = idx >> 10, cc = idx & (HID-1);
            *reinterpret_cast<float4*>(&hs[bb*HPAD + cc]) = v;
        }
        __syncthreads();

        float ar = 0.f, az = 0.f, an = 0.f;
        const float* hrow = &hs[b * HPAD];
        #pragma unroll 8
        for (int i = 0; i < 64; i++) {
            int k = i*16 + sub*4;      // interleaved k-split (bank skew)
            float4 hv = *reinterpret_cast<const float4*>(hrow + k);
            float4 wr = *reinterpret_cast<const float4*>(w_r + k);
            float4 wz = *reinterpret_cast<const float4*>(w_z + k);
            float4 wn = *reinterpret_cast<const float4*>(w_n + k);
            ar += hv.x*wr.x + hv.y*wr.y + hv.z*wr.z + hv.w*wr.w;
            az += hv.x*wz.x + hv.y*wz.y + hv.z*wz.z + hv.w*wz.w;
            an += hv.x*wn.x + hv.y*wn.y + hv.z*wn.z + hv.w*wn.w;
        }
        // reduce across the 4 sub-threads of this pair
        ar += __shfl_down_sync(0xffffffffu, ar, 2, 4);
        ar += __shfl_down_sync(0xffffffffu, ar, 1, 4);
        az += __shfl_down_sync(0xffffffffu, az, 2, 4);
        az += __shfl_down_sync(0xffffffffu, az, 1, 4);
        an += __shfl_down_sync(0xffffffffu, an, 2, 4);
        an += __shfl_down_sync(0xffffffffu, an, 1, 4);

        if (sub == 0) {
            size_t row = ((size_t)b*SEQ + s) * GATES;
            float xr = xg[row + j];
            float xz = xg[row + HID + j];
            float xn = xg[row + 2*HID + j];
            float hprev = hs[b*HPAD + j];
            float r = 1.f / (1.f + expf(-(xr + ar + br)));
            float z = 1.f / (1.f + expf(-(xz + az + bz)));
            float n = tanhf(xn + r * (an + bn_));
            float hnew = (1.f - z) * n + z * hprev;
            hdst[b*HID + j] = hnew;
            y[((size_t)b*SEQ + s)*HID + j] = hnew;
        }
        if (s + 1 < SEQ) grid_sync();
    }
}

// ---------------- launcher -----------------------------------------------------
extern "C" void kernel_launch(void* const* d_in, const int* in_sizes, int n_in,
                              void* d_out, int out_size)
{
    (void)in_sizes; (void)n_in; (void)out_size;
    const float* concepts  = (const float*)d_in[0];
    const int*   seq       = (const int*)  d_in[1];
    const float* embedding = (const float*)d_in[2];
    const float* w_ih      = (const float*)d_in[3];
    const float* w_hh      = (const float*)d_in[4];
    const float* b_ih      = (const float*)d_in[5];
    const float* b_hh      = (const float*)d_in[6];
    const float* fc_w      = (const float*)d_in[7];
    const float* fc_b      = (const float*)d_in[8];
    const float* c2h_w     = (const float*)d_in[9];
    const float* c2h_b     = (const float*)d_in[10];
    float* out = (float*)d_out;

    float *xg, *y0, *y1, *h0, *hA, *hB;
    cudaGetSymbolAddress((void**)&xg, g_xg);
    cudaGetSymbolAddress((void**)&y0, g_y0);
    cudaGetSymbolAddress((void**)&y1, g_y1);
    cudaGetSymbolAddress((void**)&h0, g_h0);
    cudaGetSymbolAddress((void**)&hA, g_hA);
    cudaGetSymbolAddress((void**)&hB, g_hB);

    // 1) initial hidden states
    h0_kernel<<<BATCH, 256>>>(concepts, c2h_w, c2h_b);

    dim3 gx(GATES/BN, MROWS/BM);     // 24 x 32
    dim3 gl(VOCAB/BN, MROWS/BM);     // 250 x 32

    // 2) layer 0 input gates (embedding gather fused into A-row indexing)
    sgemm_tn<true><<<gx, 256>>>(embedding, w_ih, b_ih, xg, seq, MROWS, GATES, HID);
    // 3) layer 0 recurrence
    gru_kernel<<<128, 256>>>(xg, w_hh, b_hh, h0, y0, hA, hB);
    // 4) layer 1 input gates
    sgemm_tn<false><<<gx, 256>>>(y0, w_ih + (size_t)GATES*HID, b_ih + GATES,
                                 xg, nullptr, MROWS, GATES, HID);
    // 5) layer 1 recurrence
    gru_kernel<<<128, 256>>>(xg, w_hh + (size_t)GATES*HID, b_hh + GATES,
                             h0 + BATCH*HID, y1, hA, hB);
    // 6) logits
    sgemm_tn<false><<<gl, 256>>>(y1, fc_w, fc_b, out, nullptr, MROWS, VOCAB, HID);
}

// round 3
// speedup vs baseline: 1.4030x; 1.4030x over previous
#include <cuda_runtime.h>
#include <math.h>

// Problem constants
#define HID    1024
#define VOCAB  32000
#define BATCH  8
#define SEQ    512
#define INDIM  768
#define MROWS  (BATCH*SEQ)      // 4096
#define GATES  (3*HID)          // 3072

// ---------------- scratch (no allocation allowed -> device globals) -----------
__device__ float g_h0[2*BATCH*HID];
__device__ float g_hA[BATCH*HID];
__device__ float g_hB[BATCH*HID];
__device__ float g_xg[(size_t)MROWS*GATES];
__device__ float g_y0[(size_t)MROWS*HID];
__device__ float g_y1[(size_t)MROWS*HID];
__device__ unsigned int          g_barcnt = 0;
__device__ volatile unsigned int g_bargen = 0;

// ---------------- h0: global context + c2h projection --------------------------
__global__ void h0_kernel(const float* __restrict__ concepts,
                          const float* __restrict__ c2h_w,
                          const float* __restrict__ c2h_b)
{
    __shared__ float ctx[INDIM];
    int b = blockIdx.x, tid = threadIdx.x;
    for (int d = tid; d < INDIM; d += blockDim.x) {
        float s = 0.f;
        #pragma unroll
        for (int n = 0; n < 16; n++) s += concepts[(b*16 + n)*INDIM + d];
        ctx[d] = s * (1.0f/16.0f);
    }
    __syncthreads();
    for (int k = tid; k < 2*HID; k += blockDim.x) {
        const float* w = c2h_w + (size_t)k*INDIM;
        float acc = 0.f;
        #pragma unroll 4
        for (int d = 0; d < INDIM; d += 4) {
            acc += ctx[d+0]*w[d+0] + ctx[d+1]*w[d+1]
                 + ctx[d+2]*w[d+2] + ctx[d+3]*w[d+3];
        }
        acc += c2h_b[k];
        int l = k >> 10, j = k & (HID-1);
        g_h0[(l*BATCH + b)*HID + j] = acc;
    }
}

// ---------------- tf32x3 tensor-core GEMM --------------------------------------
// C[M,N] = A[M,K] * B[N,K]^T + bias[N], fp32-accurate via tf32 hi/lo split.
// 128x128 tile, BK=32, 256 threads (8 warps, 2m x 4n, warp tile 64x32).
// Smem row-major [128][36] per matrix per precision, double buffered (144KB).

__device__ __forceinline__ void cvt_hi_lo(float x, float& hi, float& lo)
{
    unsigned h;
    asm("cvt.rna.tf32.f32 %0, %1;" : "=r"(h) : "f"(x));
    hi = __uint_as_float(h);
    unsigned lu;
    asm("cvt.rna.tf32.f32 %0, %1;" : "=r"(lu) : "f"(x - hi));
    lo = __uint_as_float(lu);
}

__device__ __forceinline__ void mma8(float* d, const unsigned* a, const unsigned* b)
{
    asm volatile(
        "mma.sync.aligned.m16n8k8.row.col.f32.tf32.tf32.f32 "
        "{%0,%1,%2,%3},{%4,%5,%6,%7},{%8,%9},{%0,%1,%2,%3};"
        : "+f"(d[0]), "+f"(d[1]), "+f"(d[2]), "+f"(d[3])
        : "r"(a[0]), "r"(a[1]), "r"(a[2]), "r"(a[3]), "r"(b[0]), "r"(b[1]));
}

#define GBK   32
#define GLD   36            // row length in floats (BK + 4 pad)
#define GTILE (128*GLD)     // floats per (matrix, precision) tile

template<bool GATHER>
__global__ void __launch_bounds__(256, 1)
gemm_tf32(const float* __restrict__ A, const float* __restrict__ B,
          const float* __restrict__ bias, float* __restrict__ C,
          const int* __restrict__ gidx, int M, int N, int K)
{
    extern __shared__ float sm[];
    const int tid = threadIdx.x;
    const int l   = tid & 31;
    const int wid = tid >> 5;
    const int wm  = (wid & 1) * 64;     // warp m-offset
    const int wn  = (wid >> 1) * 32;    // warp n-offset
    const int bm  = blockIdx.x * 128;
    const int bn  = blockIdx.y * 128;

    // loader mapping: 4 float4 per thread per matrix per k-tile
    int mloc[4], kloc[4];
    const float* aptr[4];
    const float* bptr[4];
    #pragma unroll
    for (int u = 0; u < 4; u++) {
        int f = tid + u*256;
        mloc[u] = f >> 3;
        kloc[u] = (f & 7) << 2;
        int ar  = GATHER ? gidx[bm + mloc[u]] : (bm + mloc[u]);
        aptr[u] = A + (size_t)ar*K + kloc[u];
        bptr[u] = B + (size_t)(bn + mloc[u])*K + kloc[u];
    }

    float acc[4][4][4];
    #pragma unroll
    for (int i = 0; i < 4; i++)
        #pragma unroll
        for (int j = 0; j < 4; j++)
            #pragma unroll
            for (int r = 0; r < 4; r++) acc[i][j][r] = 0.f;

    float4 va[4], vb[4];
    auto gload = [&](int kt) {
        #pragma unroll
        for (int u = 0; u < 4; u++) {
            va[u] = *reinterpret_cast<const float4*>(aptr[u] + kt*GBK);
            vb[u] = *reinterpret_cast<const float4*>(bptr[u] + kt*GBK);
        }
    };
    auto sstore = [&](int buf) {
        float* Ah = sm + buf*4*GTILE;
        float* Al = Ah + GTILE;
        float* Bh = Al + GTILE;
        float* Bl = Bh + GTILE;
        #pragma unroll
        for (int u = 0; u < 4; u++) {
            float4 h, lo;
            cvt_hi_lo(va[u].x, h.x, lo.x); cvt_hi_lo(va[u].y, h.y, lo.y);
            cvt_hi_lo(va[u].z, h.z, lo.z); cvt_hi_lo(va[u].w, h.w, lo.w);
            int off = mloc[u]*GLD + kloc[u];
            *reinterpret_cast<float4*>(Ah + off) = h;
            *reinterpret_cast<float4*>(Al + off) = lo;
            cvt_hi_lo(vb[u].x, h.x, lo.x); cvt_hi_lo(vb[u].y, h.y, lo.y);
            cvt_hi_lo(vb[u].z, h.z, lo.z); cvt_hi_lo(vb[u].w, h.w, lo.w);
            *reinterpret_cast<float4*>(Bh + off) = h;
            *reinterpret_cast<float4*>(Bl + off) = lo;
        }
    };

    const int nk = K / GBK;
    gload(0); sstore(0); __syncthreads();

    for (int kt = 0; kt < nk; kt++) {
        int cur = kt & 1;
        if (kt + 1 < nk) gload(kt + 1);

        const float* Ah = sm + cur*4*GTILE;
        const float* Al = Ah + GTILE;
        const float* Bh = Al + GTILE;
        const float* Bl = Bh + GTILE;

        #pragma unroll
        for (int ks = 0; ks < 4; ks++) {
            unsigned ah[4][4], al[4][4], bh[4][2], bl[4][2];
            const int kc = ks*8 + (l & 3);
            #pragma unroll
            for (int mf = 0; mf < 4; mf++) {
                int r0 = (wm + mf*16 + (l >> 2))*GLD + kc;
                ah[mf][0] = __float_as_uint(Ah[r0]);
                ah[mf][1] = __float_as_uint(Ah[r0 + 8*GLD]);
                ah[mf][2] = __float_as_uint(Ah[r0 + 4]);
                ah[mf][3] = __float_as_uint(Ah[r0 + 8*GLD + 4]);
                al[mf][0] = __float_as_uint(Al[r0]);
                al[mf][1] = __float_as_uint(Al[r0 + 8*GLD]);
                al[mf][2] = __float_as_uint(Al[r0 + 4]);
                al[mf][3] = __float_as_uint(Al[r0 + 8*GLD + 4]);
            }
            #pragma unroll
            for (int nf = 0; nf < 4; nf++) {
                int c0 = (wn + nf*8 + (l >> 2))*GLD + kc;
                bh[nf][0] = __float_as_uint(Bh[c0]);
                bh[nf][1] = __float_as_uint(Bh[c0 + 4]);
                bl[nf][0] = __float_as_uint(Bl[c0]);
                bl[nf][1] = __float_as_uint(Bl[c0 + 4]);
            }
            #pragma unroll
            for (int mf = 0; mf < 4; mf++)
                #pragma unroll
                for (int nf = 0; nf < 4; nf++) {
                    mma8(acc[mf][nf], ah[mf], bh[nf]);  // hi*hi
                    mma8(acc[mf][nf], ah[mf], bl[nf]);  // hi*lo
                    mma8(acc[mf][nf], al[mf], bh[nf]);  // lo*hi
                }
        }
        if (kt + 1 < nk) sstore(cur ^ 1);
        __syncthreads();
    }

    // epilogue with bias
    #pragma unroll
    for (int mf = 0; mf < 4; mf++) {
        int row = bm + wm + mf*16 + (l >> 2);
        #pragma unroll
        for (int nf = 0; nf < 4; nf++) {
            int col = bn + wn + nf*8 + ((l & 3) << 1);
            float b0 = bias[col], b1 = bias[col+1];
            float2 v0 = make_float2(acc[mf][nf][0] + b0, acc[mf][nf][1] + b1);
            float2 v1 = make_float2(acc[mf][nf][2] + b0, acc[mf][nf][3] + b1);
            *reinterpret_cast<float2*>(C + (size_t)row*N + col)     = v0;
            *reinterpret_cast<float2*>(C + (size_t)(row+8)*N + col) = v1;
        }
    }
}

// ---------------- persistent GRU: weights in registers --------------------------
// 128 blocks x 256 threads (8 warps). Warp w owns unit j = blk*8 + w.
// Lane l owns k-slice {i*128 + 4l + 0..3, i=0..7}: 96 weight floats in regs.
__device__ __forceinline__ void grid_sync()
{
    __threadfence();
    __syncthreads();
    if (threadIdx.x == 0) {
        unsigned int gen = g_bargen;
        if (atomicAdd(&g_barcnt, 1) == gridDim.x - 1) {
            g_barcnt = 0;
            __threadfence();
            g_bargen = gen + 1;
        } else {
            while (g_bargen == gen) { }
        }
    }
    __syncthreads();
}

__device__ __forceinline__ float wsum(float v)
{
    v += __shfl_xor_sync(0xffffffffu, v, 16);
    v += __shfl_xor_sync(0xffffffffu, v, 8);
    v += __shfl_xor_sync(0xffffffffu, v, 4);
    v += __shfl_xor_sync(0xffffffffu, v, 2);
    v += __shfl_xor_sync(0xffffffffu, v, 1);
    return v;
}

__global__ void __launch_bounds__(256, 1)
gru_kernel(const float* __restrict__ xg,    // [MROWS, 3H], row = b*SEQ+s
           const float* __restrict__ whh,   // [3H, H]
           const float* __restrict__ bhh,   // [3H]
           const float* __restrict__ h0,    // [B, H]
           float* __restrict__ y,           // [B, SEQ, H]
           float* __restrict__ hA,
           float* __restrict__ hB)
{
    __shared__ float hs[BATCH*HID];         // 32KB

    const int tid = threadIdx.x;
    const int w   = tid >> 5;
    const int l   = tid & 31;
    const int j   = blockIdx.x * 8 + w;

    // persistent weight registers
    float4 wr[8], wz[8], wn[8];
    #pragma unroll
    for (int i = 0; i < 8; i++) {
        int k = i*128 + (l << 2);
        wr[i] = *reinterpret_cast<const float4*>(whh + (size_t)(0*HID + j)*HID + k);
        wz[i] = *reinterpret_cast<const float4*>(whh + (size_t)(1*HID + j)*HID + k);
        wn[i] = *reinterpret_cast<const float4*>(whh + (size_t)(2*HID + j)*HID + k);
    }
    const float br  = bhh[j];
    const float bz  = bhh[HID + j];
    const float bn_ = bhh[2*HID + j];

    for (int s = 0; s < SEQ; s++) {
        const float* hsrc = (s == 0) ? h0 : ((s & 1) ? hA : hB);
        float*       hdst = (s & 1) ? hB : hA;

        // stage h into smem
        const float4* h4 = reinterpret_cast<const float4*>(hsrc);
        #pragma unroll
        for (int t = 0; t < 8; t++) {
            int i = tid + t*256;
            *reinterpret_cast<float4*>(&hs[i << 2]) = __ldcg(h4 + i);
        }
        __syncthreads();

        // prefetch this lane's pointwise inputs (lane l handles batch b=l)
        float xr = 0.f, xz = 0.f, xn = 0.f, hp = 0.f;
        if (l < 8) {
            size_t row = ((size_t)l*SEQ + s) * GATES;
            xr = __ldg(xg + row + j);
            xz = __ldg(xg + row + HID + j);
            xn = __ldg(xg + row + 2*HID + j);
            hp = hs[l*HID + j];
        }

        float ar[8], az[8], an[8];
        #pragma unroll
        for (int b = 0; b < 8; b++) { ar[b] = 0.f; az[b] = 0.f; an[b] = 0.f; }
        #pragma unroll
        for (int b = 0; b < 8; b++) {
            const float* hb = hs + b*HID;
            #pragma unroll
            for (int i = 0; i < 8; i++) {
                float4 h = *reinterpret_cast<const float4*>(hb + i*128 + (l << 2));
                ar[b] += h.x*wr[i].x + h.y*wr[i].y + h.z*wr[i].z + h.w*wr[i].w;
                az[b] += h.x*wz[i].x + h.y*wz[i].y + h.z*wz[i].z + h.w*wz[i].w;
                an[b] += h.x*wn[i].x + h.y*wn[i].y + h.z*wn[i].z + h.w*wn[i].w;
            }
        }

        #pragma unroll
        for (int b = 0; b < 8; b++) {
            float R  = wsum(ar[b]);
            float Z  = wsum(az[b]);
            float Nn = wsum(an[b]);
            if (l == b) {
                float r    = 1.f / (1.f + expf(-(xr + R + br)));
                float z    = 1.f / (1.f + expf(-(xz + Z + bz)));
                float n    = tanhf(xn + r * (Nn + bn_));
                float hnew = (1.f - z) * n + z * hp;
                hdst[b*HID + j] = hnew;
                y[((size_t)b*SEQ + s)*HID + j] = hnew;
            }
        }
        if (s + 1 < SEQ) grid_sync();
    }
}

// ---------------- launcher -----------------------------------------------------
extern "C" void kernel_launch(void* const* d_in, const int* in_sizes, int n_in,
                              void* d_out, int out_size)
{
    (void)in_sizes; (void)n_in; (void)out_size;
    const float* concepts  = (const float*)d_in[0];
    const int*   seq       = (const int*)  d_in[1];
    const float* embedding = (const float*)d_in[2];
    const float* w_ih      = (const float*)d_in[3];
    const float* w_hh      = (const float*)d_in[4];
    const float* b_ih      = (const float*)d_in[5];
    const float* b_hh      = (const float*)d_in[6];
    const float* fc_w      = (const float*)d_in[7];
    const float* fc_b      = (const float*)d_in[8];
    const float* c2h_w     = (const float*)d_in[9];
    const float* c2h_b     = (const float*)d_in[10];
    float* out = (float*)d_out;

    float *xg, *y0, *y1, *h0, *hA, *hB;
    cudaGetSymbolAddress((void**)&xg, g_xg);
    cudaGetSymbolAddress((void**)&y0, g_y0);
    cudaGetSymbolAddress((void**)&y1, g_y1);
    cudaGetSymbolAddress((void**)&h0, g_h0);
    cudaGetSymbolAddress((void**)&hA, g_hA);
    cudaGetSymbolAddress((void**)&hB, g_hB);

    const int smem_bytes = 2*4*GTILE*(int)sizeof(float);   // 147456
    cudaFuncSetAttribute(gemm_tf32<true>,  cudaFuncAttributeMaxDynamicSharedMemorySize, smem_bytes);
    cudaFuncSetAttribute(gemm_tf32<false>, cudaFuncAttributeMaxDynamicSharedMemorySize, smem_bytes);

    // 1) initial hidden states
    h0_kernel<<<BATCH, 256>>>(concepts, c2h_w, c2h_b);

    dim3 gx(MROWS/128, GATES/128);   // (32, 24), m-tiles inner for L2 reuse of A
    dim3 gl(MROWS/128, VOCAB/128);   // (32, 250)

    // 2) layer 0 input gates (embedding gather fused)
    gemm_tf32<true><<<gx, 256, smem_bytes>>>(embedding, w_ih, b_ih, xg, seq,
                                             MROWS, GATES, HID);
    // 3) layer 0 recurrence
    gru_kernel<<<128, 256>>>(xg, w_hh, b_hh, h0, y0, hA, hB);
    // 4) layer 1 input gates
    gemm_tf32<false><<<gx, 256, smem_bytes>>>(y0, w_ih + (size_t)GATES*HID,
                                              b_ih + GATES, xg, nullptr,
                                              MROWS, GATES, HID);
    // 5) layer 1 recurrence
    gru_kernel<<<128, 256>>>(xg, w_hh + (size_t)GATES*HID, b_hh + GATES,
                             h0 + BATCH*HID, y1, hA, hB);
    // 6) logits
    gemm_tf32<false><<<gl, 256, smem_bytes>>>(y1, fc_w, fc_b, out, nullptr,
                                              MROWS, VOCAB, HID);
}

// round 5
// speedup vs baseline: 1.7700x; 1.2616x over previous
#include <cuda_runtime.h>
#include <cuda_bf16.h>
#include <math.h>

// Problem constants
#define HID    1024
#define VOCAB  32000
#define BATCH  8
#define SEQ    512
#define INDIM  768
#define MROWS  (BATCH*SEQ)      // 4096
#define GATES  (3*HID)          // 3072

// ---------------- scratch (no allocation allowed -> device globals) -----------
__device__ float g_h0[2*BATCH*HID];
__device__ float g_hA[BATCH*HID];
__device__ float g_hB[BATCH*HID];
__device__ float g_xg[(size_t)MROWS*GATES];
__device__ float g_y0[(size_t)MROWS*HID];
__device__ float g_y1[(size_t)MROWS*HID];
__device__ unsigned int          g_barcnt = 0;
__device__ volatile unsigned int g_bargen = 0;

// ---------------- h0: global context + c2h projection --------------------------
__global__ void h0_kernel(const float* __restrict__ concepts,
                          const float* __restrict__ c2h_w,
                          const float* __restrict__ c2h_b)
{
    __shared__ float ctx[INDIM];
    int b = blockIdx.x, tid = threadIdx.x;
    for (int d = tid; d < INDIM; d += blockDim.x) {
        float s = 0.f;
        #pragma unroll
        for (int n = 0; n < 16; n++) s += concepts[(b*16 + n)*INDIM + d];
        ctx[d] = s * (1.0f/16.0f);
    }
    __syncthreads();
    for (int k = tid; k < 2*HID; k += blockDim.x) {
        const float* w = c2h_w + (size_t)k*INDIM;
        float acc = 0.f;
        #pragma unroll 4
        for (int d = 0; d < INDIM; d += 4) {
            acc += ctx[d+0]*w[d+0] + ctx[d+1]*w[d+1]
                 + ctx[d+2]*w[d+2] + ctx[d+3]*w[d+3];
        }
        acc += c2h_b[k];
        int l = k >> 10, j = k & (HID-1);
        g_h0[(l*BATCH + b)*HID + j] = acc;
    }
}

// ---------------- bf16x3 tensor-core GEMM --------------------------------------
// C[M,N] = A[M,K] * B[N,K]^T + bias[N], near-fp32 via bf16 hi/lo split (3 mma
// passes: hi*hi + hi*lo + lo*hi). 128x128 tile, BK=32, 256 threads
// (8 warps, 2m x 4n, warp tile 64x32), mma.m16n8k16.
// Smem: bf16x2 words, row length 20 words (16 + 4 pad -> conflict-free frags).

#define GLDW  20                 // b32 words per row
#define GT    (128*GLDW)         // words per tile (2560)
#define GSMEM (2*4*GT*4)         // bytes: 2 buf x {Ah,Al,Bh,Bl} = 81920

__device__ __forceinline__ unsigned pack_bf2(float a, float b)
{
    __nv_bfloat162 t = __floats2bfloat162_rn(a, b);
    return *reinterpret_cast<unsigned*>(&t);
}

__device__ __forceinline__ void split_pair(float x, float y,
                                           unsigned& hi, unsigned& lo)
{
    hi = pack_bf2(x, y);
    __nv_bfloat162 hh = *reinterpret_cast<__nv_bfloat162*>(&hi);
    lo = pack_bf2(x - __bfloat162float(hh.x), y - __bfloat162float(hh.y));
}

__device__ __forceinline__ void mma_bf16(float* d, const unsigned* a, const unsigned* b)
{
    asm volatile(
        "mma.sync.aligned.m16n8k16.row.col.f32.bf16.bf16.f32 "
        "{%0,%1,%2,%3},{%4,%5,%6,%7},{%8,%9},{%0,%1,%2,%3};"
        : "+f"(d[0]), "+f"(d[1]), "+f"(d[2]), "+f"(d[3])
        : "r"(a[0]), "r"(a[1]), "r"(a[2]), "r"(a[3]), "r"(b[0]), "r"(b[1]));
}

template<bool GATHER>
__global__ void __launch_bounds__(256, 1)
gemm_bf16x3(const float* __restrict__ A, const float* __restrict__ B,
            const float* __restrict__ bias, float* __restrict__ C,
            const int* __restrict__ gidx, int M, int N, int K)
{
    extern __shared__ unsigned sm[];
    const int tid = threadIdx.x;
    const int l   = tid & 31;
    const int wid = tid >> 5;
    const int wm  = (wid & 1) * 64;
    const int wn  = (wid >> 1) * 32;
    const int bm  = blockIdx.x * 128;
    const int bn  = blockIdx.y * 128;
    const int g   = l >> 2;         // 0..7
    const int t   = l & 3;          // 0..3

    // loader mapping: f = tid + u*256; row = f>>3, k-float = (f&7)*4
    int ploc[4];
    const float* aptr[4];
    const float* bptr[4];
    #pragma unroll
    for (int u = 0; u < 4; u++) {
        int f    = tid + u*256;
        int row  = f >> 3;
        int kf   = (f & 7) << 2;
        ploc[u]  = row*GLDW + ((f & 7) << 1);
        int ar   = GATHER ? gidx[bm + row] : (bm + row);
        aptr[u]  = A + (size_t)ar*K + kf;
        bptr[u]  = B + (size_t)(bn + row)*K + kf;
    }

    float acc[4][4][4];
    #pragma unroll
    for (int i = 0; i < 4; i++)
        #pragma unroll
        for (int j = 0; j < 4; j++)
            #pragma unroll
            for (int r = 0; r < 4; r++) acc[i][j][r] = 0.f;

    float4 va[4], vb[4];
    auto gload = [&](int kt) {
        #pragma unroll
        for (int u = 0; u < 4; u++) {
            va[u] = *reinterpret_cast<const float4*>(aptr[u] + kt*32);
            vb[u] = *reinterpret_cast<const float4*>(bptr[u] + kt*32);
        }
    };
    auto sstore = [&](int buf) {
        unsigned* Ah = sm + buf*4*GT;
        unsigned* Al = Ah + GT;
        unsigned* Bh = Al + GT;
        unsigned* Bl = Bh + GT;
        #pragma unroll
        for (int u = 0; u < 4; u++) {
            unsigned h0, l0, h1, l1;
            split_pair(va[u].x, va[u].y, h0, l0);
            split_pair(va[u].z, va[u].w, h1, l1);
            Ah[ploc[u]] = h0; Ah[ploc[u]+1] = h1;
            Al[ploc[u]] = l0; Al[ploc[u]+1] = l1;
            split_pair(vb[u].x, vb[u].y, h0, l0);
            split_pair(vb[u].z, vb[u].w, h1, l1);
            Bh[ploc[u]] = h0; Bh[ploc[u]+1] = h1;
            Bl[ploc[u]] = l0; Bl[ploc[u]+1] = l1;
        }
    };

    const int nk = K / 32;
    gload(0); sstore(0); __syncthreads();

    for (int kt = 0; kt < nk; kt++) {
        int cur = kt & 1;
        if (kt + 1 < nk) gload(kt + 1);

        const unsigned* Ah = sm + cur*4*GT;
        const unsigned* Al = Ah + GT;
        const unsigned* Bh = Al + GT;
        const unsigned* Bl = Bh + GT;

        #pragma unroll
        for (int kh = 0; kh < 2; kh++) {
            const int bp = kh * 8;
            unsigned ah[4][4], al[4][4], bh[4][2], bl[4][2];
            #pragma unroll
            for (int mf = 0; mf < 4; mf++) {
                int r0 = (wm + mf*16 + g)*GLDW + bp + t;
                ah[mf][0] = Ah[r0];
                ah[mf][1] = Ah[r0 + 8*GLDW];
                ah[mf][2] = Ah[r0 + 4];
                ah[mf][3] = Ah[r0 + 8*GLDW + 4];
                al[mf][0] = Al[r0];
                al[mf][1] = Al[r0 + 8*GLDW];
                al[mf][2] = Al[r0 + 4];
                al[mf][3] = Al[r0 + 8*GLDW + 4];
            }
            #pragma unroll
            for (int nf = 0; nf < 4; nf++) {
                int c0 = (wn + nf*8 + g)*GLDW + bp + t;
                bh[nf][0] = Bh[c0];
                bh[nf][1] = Bh[c0 + 4];
                bl[nf][0] = Bl[c0];
                bl[nf][1] = Bl[c0 + 4];
            }
            #pragma unroll
            for (int mf = 0; mf < 4; mf++)
                #pragma unroll
                for (int nf = 0; nf < 4; nf++) {
                    mma_bf16(acc[mf][nf], ah[mf], bh[nf]);  // hi*hi
                    mma_bf16(acc[mf][nf], ah[mf], bl[nf]);  // hi*lo
                    mma_bf16(acc[mf][nf], al[mf], bh[nf]);  // lo*hi
                }
        }
        if (kt + 1 < nk) sstore(cur ^ 1);
        __syncthreads();
    }

    // epilogue with bias (m16n8 accumulator layout)
    #pragma unroll
    for (int mf = 0; mf < 4; mf++) {
        int row = bm + wm + mf*16 + g;
        #pragma unroll
        for (int nf = 0; nf < 4; nf++) {
            int col = bn + wn + nf*8 + (t << 1);
            float b0 = bias[col], b1 = bias[col+1];
            float2 v0 = make_float2(acc[mf][nf][0] + b0, acc[mf][nf][1] + b1);
            float2 v1 = make_float2(acc[mf][nf][2] + b0, acc[mf][nf][3] + b1);
            *reinterpret_cast<float2*>(C + (size_t)row*N + col)     = v0;
            *reinterpret_cast<float2*>(C + (size_t)(row+8)*N + col) = v1;
        }
    }
}

// ---------------- persistent GRU: weights in regs, packed f32x2 FMA -------------
__device__ __forceinline__ void grid_sync()
{
    __threadfence();
    __syncthreads();
    if (threadIdx.x == 0) {
        unsigned int gen = g_bargen;
        if (atomicAdd(&g_barcnt, 1) == gridDim.x - 1) {
            g_barcnt = 0;
            __threadfence();
            g_bargen = gen + 1;
        } else {
            while (g_bargen == gen) { }
        }
    }
    __syncthreads();
}

__device__ __forceinline__ void fma2(unsigned long long& d,
                                     unsigned long long a,
                                     unsigned long long b)
{
    asm("fma.rn.f32x2 %0, %1, %2, %0;" : "+l"(d) : "l"(a), "l"(b));
}

__device__ __forceinline__ float hsum2(unsigned long long v)
{
    float x, y;
    asm("mov.b64 {%0,%1}, %2;" : "=f"(x), "=f"(y) : "l"(v));
    return x + y;
}

__device__ __forceinline__ float wsum(float v)
{
    v += __shfl_xor_sync(0xffffffffu, v, 16);
    v += __shfl_xor_sync(0xffffffffu, v, 8);
    v += __shfl_xor_sync(0xffffffffu, v, 4);
    v += __shfl_xor_sync(0xffffffffu, v, 2);
    v += __shfl_xor_sync(0xffffffffu, v, 1);
    return v;
}

__global__ void __launch_bounds__(256, 1)
gru_kernel(const float* __restrict__ xg,    // [MROWS, 3H], row = b*SEQ+s
           const float* __restrict__ whh,   // [3H, H]
           const float* __restrict__ bhh,   // [3H]
           const float* __restrict__ h0,    // [B, H]
           float* __restrict__ y,           // [B, SEQ, H]
           float* __restrict__ hA,
           float* __restrict__ hB)
{
    __shared__ float hs[BATCH*HID];         // 32KB

    const int tid = threadIdx.x;
    const int w   = tid >> 5;
    const int l   = tid & 31;
    const int j   = blockIdx.x * 8 + w;

    // persistent weight registers as f32x2 pairs
    ulonglong2 wr[8], wz[8], wn[8];
    #pragma unroll
    for (int i = 0; i < 8; i++) {
        int k = i*128 + (l << 2);
        wr[i] = *reinterpret_cast<const ulonglong2*>(whh + (size_t)(0*HID + j)*HID + k);
        wz[i] = *reinterpret_cast<const ulonglong2*>(whh + (size_t)(1*HID + j)*HID + k);
        wn[i] = *reinterpret_cast<const ulonglong2*>(whh + (size_t)(2*HID + j)*HID + k);
    }
    const float br  = bhh[j];
    const float bz  = bhh[HID + j];
    const float bn_ = bhh[2*HID + j];

    for (int s = 0; s < SEQ; s++) {
        const float* hsrc = (s == 0) ? h0 : ((s & 1) ? hA : hB);
        float*       hdst = (s & 1) ? hB : hA;

        // stage h into smem
        const float4* h4 = reinterpret_cast<const float4*>(hsrc);
        #pragma unroll
        for (int tt = 0; tt < 8; tt++) {
            int i = tid + tt*256;
            *reinterpret_cast<float4*>(&hs[i << 2]) = __ldcg(h4 + i);
        }
        __syncthreads();

        // prefetch pointwise inputs (lane l handles batch b=l)
        float xr = 0.f, xz = 0.f, xn = 0.f, hp = 0.f;
        if (l < 8) {
            size_t row = ((size_t)l*SEQ + s) * GATES;
            xr = __ldg(xg + row + j);
            xz = __ldg(xg + row + HID + j);
            xn = __ldg(xg + row + 2*HID + j);
            hp = hs[l*HID + j];
        }

        unsigned long long ar[8], az[8], an[8];
        #pragma unroll
        for (int b = 0; b < 8; b++) { ar[b] = 0ull; az[b] = 0ull; an[b] = 0ull; }
        #pragma unroll
        for (int b = 0; b < 8; b++) {
            const float* hb = hs + b*HID;
            #pragma unroll
            for (int i = 0; i < 8; i++) {
                ulonglong2 h2 = *reinterpret_cast<const ulonglong2*>(hb + i*128 + (l << 2));
                fma2(ar[b], h2.x, wr[i].x);
                fma2(ar[b], h2.y, wr[i].y);
                fma2(az[b], h2.x, wz[i].x);
                fma2(az[b], h2.y, wz[i].y);
                fma2(an[b], h2.x, wn[i].x);
                fma2(an[b], h2.y, wn[i].y);
            }
        }

        #pragma unroll
        for (int b = 0; b < 8; b++) {
            float R  = wsum(hsum2(ar[b]));
            float Z  = wsum(hsum2(az[b]));
            float Nn = wsum(hsum2(an[b]));
            if (l == b) {
                float r    = 1.f / (1.f + __expf(-(xr + R + br)));
                float z    = 1.f / (1.f + __expf(-(xz + Z + bz)));
                float n    = tanhf(xn + r * (Nn + bn_));
                float hnew = (1.f - z) * n + z * hp;
                hdst[b*HID + j] = hnew;
                y[((size_t)b*SEQ + s)*HID + j] = hnew;
            }
        }
        if (s + 1 < SEQ) grid_sync();
    }
}

// ---------------- launcher -----------------------------------------------------
extern "C" void kernel_launch(void* const* d_in, const int* in_sizes, int n_in,
                              void* d_out, int out_size)
{
    (void)in_sizes; (void)n_in; (void)out_size;
    const float* concepts  = (const float*)d_in[0];
    const int*   seq       = (const int*)  d_in[1];
    const float* embedding = (const float*)d_in[2];
    const float* w_ih      = (const float*)d_in[3];
    const float* w_hh      = (const float*)d_in[4];
    const float* b_ih      = (const float*)d_in[5];
    const float* b_hh      = (const float*)d_in[6];
    const float* fc_w      = (const float*)d_in[7];
    const float* fc_b      = (const float*)d_in[8];
    const float* c2h_w     = (const float*)d_in[9];
    const float* c2h_b     = (const float*)d_in[10];
    float* out = (float*)d_out;

    float *xg, *y0, *y1, *h0, *hA, *hB;
    cudaGetSymbolAddress((void**)&xg, g_xg);
    cudaGetSymbolAddress((void**)&y0, g_y0);
    cudaGetSymbolAddress((void**)&y1, g_y1);
    cudaGetSymbolAddress((void**)&h0, g_h0);
    cudaGetSymbolAddress((void**)&hA, g_hA);
    cudaGetSymbolAddress((void**)&hB, g_hB);

    cudaFuncSetAttribute(gemm_bf16x3<true>,  cudaFuncAttributeMaxDynamicSharedMemorySize, GSMEM);
    cudaFuncSetAttribute(gemm_bf16x3<false>, cudaFuncAttributeMaxDynamicSharedMemorySize, GSMEM);

    // 1) initial hidden states
    h0_kernel<<<BATCH, 256>>>(concepts, c2h_w, c2h_b);

    dim3 gx(MROWS/128, GATES/128);   // (32, 24)
    dim3 gl(MROWS/128, VOCAB/128);   // (32, 250)

    // 2) layer 0 input gates (embedding gather fused)
    gemm_bf16x3<true><<<gx, 256, GSMEM>>>(embedding, w_ih, b_ih, xg, seq,
                                          MROWS, GATES, HID);
    // 3) layer 0 recurrence
    gru_kernel<<<128, 256>>>(xg, w_hh, b_hh, h0, y0, hA, hB);
    // 4) layer 1 input gates
    gemm_bf16x3<false><<<gx, 256, GSMEM>>>(y0, w_ih + (size_t)GATES*HID,
                                           b_ih + GATES, xg, nullptr,
                                           MROWS, GATES, HID);
    // 5) layer 1 recurrence
    gru_kernel<<<128, 256>>>(xg, w_hh + (size_t)GATES*HID, b_hh + GATES,
                             h0 + BATCH*HID, y1, hA, hB);
    // 6) logits
    gemm_bf16x3<false><<<gl, 256, GSMEM>>>(y1, fc_w, fc_b, out, nullptr,
                                           MROWS, VOCAB, HID);
}